// round 12
// baseline (speedup 1.0000x reference)
#include <cuda_runtime.h>
#include <cstdint>

#define NN 100000
#define F1 128
#define FH 64
#define FO 32
#define EMAX 1600000
#define NSCAN_BLK 196            // ceil(100000/512)

// Scratch (no allocations allowed).
__device__ int   g_deg[NN];                     // zero at load; re-zeroed by k_scatter
__device__ int   g_cur[NN];
__device__ int   g_off[NN + 1];
__device__ unsigned long long g_lb[NSCAN_BLK];  // lookback: (flag<<32)|value; zeroed by k_scatter
__device__ float g_dinv[NN];
__device__ int2  g_edge[EMAX];                  // (src, norm) grouped by dst
__device__ float g_h1[(size_t)NN * FH];         // x @ W1
__device__ float g_a1[(size_t)NN * FH];         // layer-1 activations (post ReLU)
__device__ float g_h3[(size_t)NN * FO];         // a1 @ W2

#define FMA2(acc, aa, ww) \
    asm("fma.rn.f32x2 %0, %1, %2, %0;" : "+l"(acc) : "l"(aa), "l"(ww))
#define BCAST2(aa, a) \
    asm("mov.b64 %0, {%1, %1};" : "=l"(aa) : "f"(a))

// ---------------------------------------------------------------------------
__global__ void k_deg(const int* __restrict__ ei, int E) {
    int i = blockIdx.x * blockDim.x + threadIdx.x;
    if (i < E) atomicAdd(&g_deg[ei[E + i]], 1);
}

// Single-pass decoupled-lookback exclusive scan of g_deg -> g_off,
// fused with cursor reset and dinv computation.
__global__ __launch_bounds__(512) void k_scan() {
    __shared__ int sh[512];
    __shared__ int s_prev;
    int t = threadIdx.x;
    int b = blockIdx.x;
    int i = b * 512 + t;
    int deg = (i < NN) ? g_deg[i] : 0;
    sh[t] = deg;
    for (int d = 1; d < 512; d <<= 1) {
        __syncthreads();
        int u = (t >= d) ? sh[t - d] : 0;
        __syncthreads();
        sh[t] += u;
    }
    __syncthreads();
    int agg = sh[511];

    if (t == 0) {
        if (b == 0) atomicExch(&g_lb[0], (2ULL << 32) | (unsigned)agg);
        else        atomicExch(&g_lb[b], (1ULL << 32) | (unsigned)agg);
    }

    if (b > 0 && t < 32) {                 // warp-parallel lookback
        int excl = 0;
        int hi = b - 1;
        for (;;) {
            int idx = hi - t;
            unsigned long long w = 0;
            if (idx >= 0) w = *(volatile unsigned long long*)&g_lb[idx];
            unsigned f = (idx >= 0) ? (unsigned)(w >> 32) : 2u;
            if (__ballot_sync(0xffffffffu, f == 0u)) continue;   // retry window
            int v = (int)(unsigned)(w & 0xffffffffULL);
            unsigned haspfx = __ballot_sync(0xffffffffu, f == 2u && idx >= 0);
            if (haspfx) {
                int first = __ffs(haspfx) - 1;   // nearest lane with a prefix
                int contrib = (idx >= 0 && t <= first) ? v : 0;
                #pragma unroll
                for (int o = 16; o; o >>= 1) contrib += __shfl_down_sync(0xffffffffu, contrib, o);
                excl += __shfl_sync(0xffffffffu, contrib, 0);
                break;
            } else {
                int contrib = (idx >= 0) ? v : 0;
                #pragma unroll
                for (int o = 16; o; o >>= 1) contrib += __shfl_down_sync(0xffffffffu, contrib, o);
                excl += __shfl_sync(0xffffffffu, contrib, 0);
                hi -= 32;
            }
        }
        if (t == 0) {
            s_prev = excl;
            atomicExch(&g_lb[b], (2ULL << 32) | (unsigned)(excl + agg));
        }
    } else if (b == 0 && t == 0) {
        s_prev = 0;
    }
    __syncthreads();

    if (i < NN) {
        g_off[i] = s_prev + sh[t] - deg;   // exclusive
        g_cur[i] = 0;
        g_dinv[i] = rsqrtf((float)deg + 1.0f);   // +1 self-loop
    }
    if (b == NSCAN_BLK - 1 && t == 511) g_off[NN] = s_prev + sh[511];
}

// Scatter edges into destination-grouped order; also reset deg/lookback state
// so the next call (graph replay) starts from the module-load invariant.
__global__ void k_scatter(const int* __restrict__ ei, int E) {
    int e = blockIdx.x * blockDim.x + threadIdx.x;
    if (e >= E) return;
    int s = ei[e];
    int d = ei[E + e];
    float norm = g_dinv[s] * g_dinv[d];
    int pos = g_off[d] + atomicAdd(&g_cur[d], 1);
    g_edge[pos] = make_int2(s, __float_as_int(norm));
    if (e < NN) g_deg[e] = 0;
    if (e < NSCAN_BLK) g_lb[e] = 0ULL;
}

// ---------------------------------------------------------------------------
// GEMM1: h1[NN,64] = x[NN,128] @ W1[128,64].
// 64 rows/block, 256 threads, 4 rows x 4 cols per thread, FFMA2 math,
// K chunked by 4 with float4 activation loads (fewer LDS wavefronts).
__global__ __launch_bounds__(256) void k_gemm1(const float* __restrict__ x,
                                               const float* __restrict__ W) {
    __shared__ float Ws[F1 * FH];   // 32 KB  [k][col]
    __shared__ float xs[64 * F1];   // 32 KB  [r][k]
    int tid = threadIdx.x;
    float4* Ws4 = (float4*)Ws;
    const float4* W4 = (const float4*)W;
    for (int i = tid; i < F1 * FH / 4; i += 256) Ws4[i] = W4[i];
    int row0 = blockIdx.x * 64;
    const float4* x4 = (const float4*)x;
    float4* xs4 = (float4*)xs;
    for (int i = tid; i < 64 * F1 / 4; i += 256) {
        int row = row0 + (i >> 5);                 // 32 float4 per row
        xs4[i] = (row < NN) ? x4[(size_t)row * 32 + (i & 31)]
                            : make_float4(0.f, 0.f, 0.f, 0.f);
    }
    __syncthreads();

    int tx = tid & 15;              // cols 4tx..4tx+3
    int ty = tid >> 4;              // rows 4ty..4ty+3
    const float* xr = xs + 4 * ty * F1;
    const ulonglong2* Wp = (const ulonglong2*)Ws;  // 16 per k-row (64 cols)
    unsigned long long acc[4][2] = {};             // 0 bits == {0.f, 0.f}

    #define G1_STEP(KK, CMP)                                               \
        do {                                                               \
            ulonglong2 w = Wp[(k + KK) * 16 + tx];                         \
            unsigned long long aa;                                         \
            BCAST2(aa, a0.CMP); FMA2(acc[0][0], aa, w.x); FMA2(acc[0][1], aa, w.y); \
            BCAST2(aa, a1.CMP); FMA2(acc[1][0], aa, w.x); FMA2(acc[1][1], aa, w.y); \
            BCAST2(aa, a2.CMP); FMA2(acc[2][0], aa, w.x); FMA2(acc[2][1], aa, w.y); \
            BCAST2(aa, a3.CMP); FMA2(acc[3][0], aa, w.x); FMA2(acc[3][1], aa, w.y); \
        } while (0)

    #pragma unroll 4
    for (int k = 0; k < F1; k += 4) {
        float4 a0 = *(const float4*)(xr + 0 * F1 + k);
        float4 a1 = *(const float4*)(xr + 1 * F1 + k);
        float4 a2 = *(const float4*)(xr + 2 * F1 + k);
        float4 a3 = *(const float4*)(xr + 3 * F1 + k);
        G1_STEP(0, x); G1_STEP(1, y); G1_STEP(2, z); G1_STEP(3, w);
    }
    #undef G1_STEP

    ulonglong2* h1v = (ulonglong2*)g_h1;           // 16 per row
    #pragma unroll
    for (int j = 0; j < 4; j++) {
        int row = row0 + 4 * ty + j;
        if (row < NN) h1v[(size_t)row * 16 + tx] = make_ulonglong2(acc[j][0], acc[j][1]);
    }
}

// Aggregation layer 1 (+ self-loop + bias + ReLU): ONE WARP PER NODE.
// Two edges in flight (half-warp each, 16 feature-chunks of float4), final
// cross-half shfl reduction. Uniform trip count -> no intra-warp divergence.
__global__ __launch_bounds__(256) void k_agg1(const float* __restrict__ b1) {
    int node = (blockIdx.x * 256 + threadIdx.x) >> 5;
    int lane = threadIdx.x & 31;
    if (node >= NN) return;
    int half = lane >> 4;            // which edge of the pair
    int fl   = lane & 15;            // feature chunk
    int off = g_off[node];
    int n   = g_off[node + 1] - off;
    const float4* h1v = (const float4*)g_h1;   // 16 float4 per row
    float4 acc = make_float4(0.f, 0.f, 0.f, 0.f);
    int i = 0;
    for (; i + 2 <= n; i += 2) {
        int2 e = g_edge[off + i + half];
        float4 p = h1v[(size_t)e.x * 16 + fl];
        float nm = __int_as_float(e.y);
        acc.x = fmaf(p.x, nm, acc.x); acc.y = fmaf(p.y, nm, acc.y);
        acc.z = fmaf(p.z, nm, acc.z); acc.w = fmaf(p.w, nm, acc.w);
    }
    if (i + half < n) {              // remainder edge on half 0 only
        int2 e = g_edge[off + i + half];
        float4 p = h1v[(size_t)e.x * 16 + fl];
        float nm = __int_as_float(e.y);
        acc.x = fmaf(p.x, nm, acc.x); acc.y = fmaf(p.y, nm, acc.y);
        acc.z = fmaf(p.z, nm, acc.z); acc.w = fmaf(p.w, nm, acc.w);
    }
    // cross-half reduction (lane L <- L ^ 16)
    acc.x += __shfl_xor_sync(0xffffffffu, acc.x, 16);
    acc.y += __shfl_xor_sync(0xffffffffu, acc.y, 16);
    acc.z += __shfl_xor_sync(0xffffffffu, acc.z, 16);
    acc.w += __shfl_xor_sync(0xffffffffu, acc.w, 16);

    float di = g_dinv[node], w = di * di;
    float4 hs = h1v[(size_t)node * 16 + fl];
    float4 bb = ((const float4*)b1)[fl];
    acc.x = fmaxf(fmaf(hs.x, w, acc.x) + bb.x, 0.f);
    acc.y = fmaxf(fmaf(hs.y, w, acc.y) + bb.y, 0.f);
    acc.z = fmaxf(fmaf(hs.z, w, acc.z) + bb.z, 0.f);
    acc.w = fmaxf(fmaf(hs.w, w, acc.w) + bb.w, 0.f);
    if (half == 0)
        ((float4*)g_a1)[(size_t)node * 16 + fl] = acc;
}

// ---------------------------------------------------------------------------
// GEMM2: h3[NN,32] = a1[NN,64] @ W2[64,32].
// 128 rows/block, 256 threads, 4 rows x 4 cols per thread, FFMA2 math,
// K chunked by 4 with float4 activation loads.
__global__ __launch_bounds__(256) void k_gemm2(const float* __restrict__ W) {
    __shared__ float Ws[FH * FO];    // 8 KB
    __shared__ float xs[128 * FH];   // 32 KB
    int tid = threadIdx.x;
    float4* Ws4 = (float4*)Ws;
    const float4* W4 = (const float4*)W;
    for (int i = tid; i < FH * FO / 4; i += 256) Ws4[i] = W4[i];
    int row0 = blockIdx.x * 128;
    const float4* x4 = (const float4*)g_a1;
    float4* xs4 = (float4*)xs;
    for (int i = tid; i < 128 * FH / 4; i += 256) {
        int row = row0 + (i >> 4);                 // 16 float4 per row
        xs4[i] = (row < NN) ? x4[(size_t)row * 16 + (i & 15)]
                            : make_float4(0.f, 0.f, 0.f, 0.f);
    }
    __syncthreads();

    int tx = tid & 7;               // cols 4tx..4tx+3
    int ty = tid >> 3;              // rows 4ty..4ty+3
    const float* xr = xs + 4 * ty * FH;
    const ulonglong2* Wp = (const ulonglong2*)Ws;  // 8 per k-row (32 cols)
    unsigned long long acc[4][2] = {};

    #define G2_STEP(KK, CMP)                                               \
        do {                                                               \
            ulonglong2 w = Wp[(k + KK) * 8 + tx];                          \
            unsigned long long aa;                                         \
            BCAST2(aa, a0.CMP); FMA2(acc[0][0], aa, w.x); FMA2(acc[0][1], aa, w.y); \
            BCAST2(aa, a1.CMP); FMA2(acc[1][0], aa, w.x); FMA2(acc[1][1], aa, w.y); \
            BCAST2(aa, a2.CMP); FMA2(acc[2][0], aa, w.x); FMA2(acc[2][1], aa, w.y); \
            BCAST2(aa, a3.CMP); FMA2(acc[3][0], aa, w.x); FMA2(acc[3][1], aa, w.y); \
        } while (0)

    #pragma unroll 4
    for (int k = 0; k < FH; k += 4) {
        float4 a0 = *(const float4*)(xr + 0 * FH + k);
        float4 a1 = *(const float4*)(xr + 1 * FH + k);
        float4 a2 = *(const float4*)(xr + 2 * FH + k);
        float4 a3 = *(const float4*)(xr + 3 * FH + k);
        G2_STEP(0, x); G2_STEP(1, y); G2_STEP(2, z); G2_STEP(3, w);
    }
    #undef G2_STEP

    ulonglong2* h3v = (ulonglong2*)g_h3;           // 8 per row
    #pragma unroll
    for (int j = 0; j < 4; j++) {
        int row = row0 + 4 * ty + j;
        if (row < NN) h3v[(size_t)row * 8 + tx] = make_ulonglong2(acc[j][0], acc[j][1]);
    }
}

// Aggregation layer 2 (+ self-loop + bias): ONE WARP PER NODE.
// Four edges in flight (8 lanes each), quad shfl reduction, store to d_out.
__global__ __launch_bounds__(256) void k_agg2(float* __restrict__ out,
                                              const float* __restrict__ b2) {
    int node = (blockIdx.x * 256 + threadIdx.x) >> 5;
    int lane = threadIdx.x & 31;
    if (node >= NN) return;
    int q  = lane >> 3;              // which edge of the quad
    int fl = lane & 7;               // feature chunk
    int off = g_off[node];
    int n   = g_off[node + 1] - off;
    const float4* h3v = (const float4*)g_h3;   // 8 float4 per row
    float4 acc = make_float4(0.f, 0.f, 0.f, 0.f);
    int i = 0;
    for (; i + 4 <= n; i += 4) {
        int2 e = g_edge[off + i + q];
        float4 p = h3v[(size_t)e.x * 8 + fl];
        float nm = __int_as_float(e.y);
        acc.x = fmaf(p.x, nm, acc.x); acc.y = fmaf(p.y, nm, acc.y);
        acc.z = fmaf(p.z, nm, acc.z); acc.w = fmaf(p.w, nm, acc.w);
    }
    if (i + q < n) {                 // ragged remainder, handled per quad
        int2 e = g_edge[off + i + q];
        float4 p = h3v[(size_t)e.x * 8 + fl];
        float nm = __int_as_float(e.y);
        acc.x = fmaf(p.x, nm, acc.x); acc.y = fmaf(p.y, nm, acc.y);
        acc.z = fmaf(p.z, nm, acc.z); acc.w = fmaf(p.w, nm, acc.w);
    }
    // quad reduction (xor 8, then xor 16)
    acc.x += __shfl_xor_sync(0xffffffffu, acc.x, 8);
    acc.y += __shfl_xor_sync(0xffffffffu, acc.y, 8);
    acc.z += __shfl_xor_sync(0xffffffffu, acc.z, 8);
    acc.w += __shfl_xor_sync(0xffffffffu, acc.w, 8);
    acc.x += __shfl_xor_sync(0xffffffffu, acc.x, 16);
    acc.y += __shfl_xor_sync(0xffffffffu, acc.y, 16);
    acc.z += __shfl_xor_sync(0xffffffffu, acc.z, 16);
    acc.w += __shfl_xor_sync(0xffffffffu, acc.w, 16);

    float di = g_dinv[node], w = di * di;
    float4 hs = h3v[(size_t)node * 8 + fl];
    float4 bb = ((const float4*)b2)[fl];
    acc.x = fmaf(hs.x, w, acc.x) + bb.x;
    acc.y = fmaf(hs.y, w, acc.y) + bb.y;
    acc.z = fmaf(hs.z, w, acc.z) + bb.z;
    acc.w = fmaf(hs.w, w, acc.w) + bb.w;
    if (q == 0)
        ((float4*)out)[(size_t)node * 8 + fl] = acc;
}

// ---------------------------------------------------------------------------
namespace {
struct Ctx {
    cudaStream_t s2;
    cudaEvent_t e_fork, e_join;
    Ctx() {
        cudaStreamCreateWithFlags(&s2, cudaStreamNonBlocking);
        cudaEventCreateWithFlags(&e_fork, cudaEventDisableTiming);
        cudaEventCreateWithFlags(&e_join, cudaEventDisableTiming);
    }
};
}

extern "C" void kernel_launch(void* const* d_in, const int* in_sizes, int n_in,
                              void* d_out, int out_size) {
    static Ctx ctx;   // created on first (uncaptured) correctness call

    const float* x  = (const float*)d_in[0];
    const int*   ei = (const int*)d_in[1];     // int32 (JAX x64 disabled)
    const float* W1 = (const float*)d_in[2];
    const float* b1 = (const float*)d_in[3];
    const float* W2 = (const float*)d_in[4];
    const float* b2 = (const float*)d_in[5];
    float* out = (float*)d_out;

    const int E = in_sizes[1] / 2;

    // Fork: graph preprocessing on ctx.s2 concurrently with GEMM1.
    cudaEventRecord(ctx.e_fork, 0);
    cudaStreamWaitEvent(ctx.s2, ctx.e_fork, 0);

    k_deg<<<(E + 255) / 256, 256, 0, ctx.s2>>>(ei, E);
    k_scan<<<NSCAN_BLK, 512, 0, ctx.s2>>>();
    k_scatter<<<(E + 255) / 256, 256, 0, ctx.s2>>>(ei, E);
    cudaEventRecord(ctx.e_join, ctx.s2);

    k_gemm1<<<(NN + 63) / 64, 256>>>(x, W1);

    // Join: aggregation needs both h1 and the grouped edge list.
    cudaStreamWaitEvent(0, ctx.e_join, 0);

    k_agg1<<<(unsigned)(((long)NN * 32 + 255) / 256), 256>>>(b1);
    k_gemm2<<<(NN + 127) / 128, 256>>>(W2);
    k_agg2<<<(unsigned)(((long)NN * 32 + 255) / 256), 256>>>(out, b2);
}

// round 13
// speedup vs baseline: 1.1298x; 1.1298x over previous
#include <cuda_runtime.h>
#include <cuda_fp16.h>
#include <cstdint>

#define NN 100000
#define F1 128
#define FH 64
#define FO 32
#define EMAX 1600000
#define NSCAN_BLK 196            // ceil(100000/512)

// Scratch (no allocations allowed).
__device__ int   g_deg[NN];                     // zero at load; re-zeroed by k_scatter
__device__ int   g_cur[NN];
__device__ int   g_off[NN + 1];
__device__ unsigned long long g_lb[NSCAN_BLK];  // lookback: (flag<<32)|value; zeroed by k_scatter
__device__ float g_dinv[NN];
__device__ int2  g_edge[EMAX];                  // (src, norm) grouped by dst
__device__ __half g_h1h[(size_t)NN * FH];       // x @ W1, fp16 (gather payload)
__device__ float  g_a1[(size_t)NN * FH];        // layer-1 activations (post ReLU), fp32
__device__ __half g_h3h[(size_t)NN * FO];       // a1 @ W2, fp16 (gather payload)

#define FMA2(acc, aa, ww) \
    asm("fma.rn.f32x2 %0, %1, %2, %0;" : "+l"(acc) : "l"(aa), "l"(ww))
#define BCAST2(aa, a) \
    asm("mov.b64 %0, {%1, %1};" : "=l"(aa) : "f"(a))

// ---------------------------------------------------------------------------
__global__ void k_deg(const int* __restrict__ ei, int E) {
    int i = blockIdx.x * blockDim.x + threadIdx.x;
    if (i < E) atomicAdd(&g_deg[ei[E + i]], 1);
}

// Single-pass decoupled-lookback exclusive scan of g_deg -> g_off,
// fused with cursor reset and dinv computation.
__global__ __launch_bounds__(512) void k_scan() {
    __shared__ int sh[512];
    __shared__ int s_prev;
    int t = threadIdx.x;
    int b = blockIdx.x;
    int i = b * 512 + t;
    int deg = (i < NN) ? g_deg[i] : 0;
    sh[t] = deg;
    for (int d = 1; d < 512; d <<= 1) {
        __syncthreads();
        int u = (t >= d) ? sh[t - d] : 0;
        __syncthreads();
        sh[t] += u;
    }
    __syncthreads();
    int agg = sh[511];

    if (t == 0) {
        if (b == 0) atomicExch(&g_lb[0], (2ULL << 32) | (unsigned)agg);
        else        atomicExch(&g_lb[b], (1ULL << 32) | (unsigned)agg);
    }

    if (b > 0 && t < 32) {                 // warp-parallel lookback
        int excl = 0;
        int hi = b - 1;
        for (;;) {
            int idx = hi - t;
            unsigned long long w = 0;
            if (idx >= 0) w = *(volatile unsigned long long*)&g_lb[idx];
            unsigned f = (idx >= 0) ? (unsigned)(w >> 32) : 2u;
            if (__ballot_sync(0xffffffffu, f == 0u)) continue;   // retry window
            int v = (int)(unsigned)(w & 0xffffffffULL);
            unsigned haspfx = __ballot_sync(0xffffffffu, f == 2u && idx >= 0);
            if (haspfx) {
                int first = __ffs(haspfx) - 1;   // nearest lane with a prefix
                int contrib = (idx >= 0 && t <= first) ? v : 0;
                #pragma unroll
                for (int o = 16; o; o >>= 1) contrib += __shfl_down_sync(0xffffffffu, contrib, o);
                excl += __shfl_sync(0xffffffffu, contrib, 0);
                break;
            } else {
                int contrib = (idx >= 0) ? v : 0;
                #pragma unroll
                for (int o = 16; o; o >>= 1) contrib += __shfl_down_sync(0xffffffffu, contrib, o);
                excl += __shfl_sync(0xffffffffu, contrib, 0);
                hi -= 32;
            }
        }
        if (t == 0) {
            s_prev = excl;
            atomicExch(&g_lb[b], (2ULL << 32) | (unsigned)(excl + agg));
        }
    } else if (b == 0 && t == 0) {
        s_prev = 0;
    }
    __syncthreads();

    if (i < NN) {
        g_off[i] = s_prev + sh[t] - deg;   // exclusive
        g_cur[i] = 0;
        g_dinv[i] = rsqrtf((float)deg + 1.0f);   // +1 self-loop
    }
    if (b == NSCAN_BLK - 1 && t == 511) g_off[NN] = s_prev + sh[511];
}

// Scatter edges into destination-grouped order; also reset deg/lookback state
// so the next call (graph replay) starts from the module-load invariant.
__global__ void k_scatter(const int* __restrict__ ei, int E) {
    int e = blockIdx.x * blockDim.x + threadIdx.x;
    if (e >= E) return;
    int s = ei[e];
    int d = ei[E + e];
    float norm = g_dinv[s] * g_dinv[d];
    int pos = g_off[d] + atomicAdd(&g_cur[d], 1);
    g_edge[pos] = make_int2(s, __float_as_int(norm));
    if (e < NN) g_deg[e] = 0;
    if (e < NSCAN_BLK) g_lb[e] = 0ULL;
}

// ---------------------------------------------------------------------------
// GEMM1: h1[NN,64] = x[NN,128] @ W1[128,64].
// 64 rows/block, 256 threads, 4 rows x 4 cols per thread, FFMA2 math,
// K chunked by 4 with float4 activation loads. Output stored as fp16.
__global__ __launch_bounds__(256) void k_gemm1(const float* __restrict__ x,
                                               const float* __restrict__ W) {
    __shared__ float Ws[F1 * FH];   // 32 KB  [k][col]
    __shared__ float xs[64 * F1];   // 32 KB  [r][k]
    int tid = threadIdx.x;
    float4* Ws4 = (float4*)Ws;
    const float4* W4 = (const float4*)W;
    for (int i = tid; i < F1 * FH / 4; i += 256) Ws4[i] = W4[i];
    int row0 = blockIdx.x * 64;
    const float4* x4 = (const float4*)x;
    float4* xs4 = (float4*)xs;
    for (int i = tid; i < 64 * F1 / 4; i += 256) {
        int row = row0 + (i >> 5);                 // 32 float4 per row
        xs4[i] = (row < NN) ? x4[(size_t)row * 32 + (i & 31)]
                            : make_float4(0.f, 0.f, 0.f, 0.f);
    }
    __syncthreads();

    int tx = tid & 15;              // cols 4tx..4tx+3
    int ty = tid >> 4;              // rows 4ty..4ty+3
    const float* xr = xs + 4 * ty * F1;
    const ulonglong2* Wp = (const ulonglong2*)Ws;  // 16 per k-row (64 cols)
    unsigned long long acc[4][2] = {};             // 0 bits == {0.f, 0.f}

    #define G1_STEP(KK, CMP)                                               \
        do {                                                               \
            ulonglong2 w = Wp[(k + KK) * 16 + tx];                         \
            unsigned long long aa;                                         \
            BCAST2(aa, a0.CMP); FMA2(acc[0][0], aa, w.x); FMA2(acc[0][1], aa, w.y); \
            BCAST2(aa, a1.CMP); FMA2(acc[1][0], aa, w.x); FMA2(acc[1][1], aa, w.y); \
            BCAST2(aa, a2.CMP); FMA2(acc[2][0], aa, w.x); FMA2(acc[2][1], aa, w.y); \
            BCAST2(aa, a3.CMP); FMA2(acc[3][0], aa, w.x); FMA2(acc[3][1], aa, w.y); \
        } while (0)

    #pragma unroll 4
    for (int k = 0; k < F1; k += 4) {
        float4 a0 = *(const float4*)(xr + 0 * F1 + k);
        float4 a1 = *(const float4*)(xr + 1 * F1 + k);
        float4 a2 = *(const float4*)(xr + 2 * F1 + k);
        float4 a3 = *(const float4*)(xr + 3 * F1 + k);
        G1_STEP(0, x); G1_STEP(1, y); G1_STEP(2, z); G1_STEP(3, w);
    }
    #undef G1_STEP

    uint2* h1v = (uint2*)g_h1h;                    // 16 uint2 (4 half each) per row
    #pragma unroll
    for (int j = 0; j < 4; j++) {
        int row = row0 + 4 * ty + j;
        if (row < NN) {
            float2 f01 = *(float2*)&acc[j][0];
            float2 f23 = *(float2*)&acc[j][1];
            __half2 h01 = __float22half2_rn(f01);
            __half2 h23 = __float22half2_rn(f23);
            uint2 u;
            u.x = *(unsigned*)&h01;
            u.y = *(unsigned*)&h23;
            h1v[(size_t)row * 16 + tx] = u;
        }
    }
}

// Aggregation layer 1 (+ self-loop + bias + ReLU): 16 lanes per dst node,
// each lane gathers 4 fp16 features (uint2 = 8B) per edge; fp32 accumulate.
__global__ __launch_bounds__(256) void k_agg1(const float* __restrict__ b1) {
    int gid = blockIdx.x * 256 + threadIdx.x;
    int node = gid >> 4;
    int lane = threadIdx.x & 15;
    if (node >= NN) return;
    int off = g_off[node];
    int n   = g_off[node + 1] - off;
    const uint2* h1v = (const uint2*)g_h1h;    // 16 uint2 per row
    float4 acc = make_float4(0.f, 0.f, 0.f, 0.f);

    #define AGG1_TERM(u, nm)                                              \
        do {                                                              \
            __half2 hl = *(__half2*)&(u).x;                               \
            __half2 hh = *(__half2*)&(u).y;                               \
            float2 pl = __half22float2(hl);                               \
            float2 ph = __half22float2(hh);                               \
            acc.x = fmaf(pl.x, nm, acc.x); acc.y = fmaf(pl.y, nm, acc.y); \
            acc.z = fmaf(ph.x, nm, acc.z); acc.w = fmaf(ph.y, nm, acc.w); \
        } while (0)

    int i = 0;
    for (; i + 1 < n; i += 2) {
        int2 e0 = g_edge[off + i];
        int2 e1 = g_edge[off + i + 1];
        uint2 u0 = h1v[(size_t)e0.x * 16 + lane];
        uint2 u1 = h1v[(size_t)e1.x * 16 + lane];
        float n0 = __int_as_float(e0.y), n1 = __int_as_float(e1.y);
        AGG1_TERM(u0, n0);
        AGG1_TERM(u1, n1);
    }
    if (i < n) {
        int2 e0 = g_edge[off + i];
        uint2 u0 = h1v[(size_t)e0.x * 16 + lane];
        float n0 = __int_as_float(e0.y);
        AGG1_TERM(u0, n0);
    }
    {   // self-loop
        float di = g_dinv[node];
        float w = di * di;
        uint2 us = h1v[(size_t)node * 16 + lane];
        AGG1_TERM(us, w);
    }
    #undef AGG1_TERM

    float4 bb = ((const float4*)b1)[lane];
    acc.x = fmaxf(acc.x + bb.x, 0.f);
    acc.y = fmaxf(acc.y + bb.y, 0.f);
    acc.z = fmaxf(acc.z + bb.z, 0.f);
    acc.w = fmaxf(acc.w + bb.w, 0.f);
    ((float4*)g_a1)[(size_t)node * 16 + lane] = acc;
}

// ---------------------------------------------------------------------------
// GEMM2: h3[NN,32] = a1[NN,64] @ W2[64,32].
// 128 rows/block, 256 threads, 4 rows x 4 cols per thread, FFMA2 math,
// K chunked by 4 with float4 activation loads. Output stored as fp16.
__global__ __launch_bounds__(256) void k_gemm2(const float* __restrict__ W) {
    __shared__ float Ws[FH * FO];    // 8 KB
    __shared__ float xs[128 * FH];   // 32 KB
    int tid = threadIdx.x;
    float4* Ws4 = (float4*)Ws;
    const float4* W4 = (const float4*)W;
    for (int i = tid; i < FH * FO / 4; i += 256) Ws4[i] = W4[i];
    int row0 = blockIdx.x * 128;
    const float4* x4 = (const float4*)g_a1;
    float4* xs4 = (float4*)xs;
    for (int i = tid; i < 128 * FH / 4; i += 256) {
        int row = row0 + (i >> 4);                 // 16 float4 per row
        xs4[i] = (row < NN) ? x4[(size_t)row * 16 + (i & 15)]
                            : make_float4(0.f, 0.f, 0.f, 0.f);
    }
    __syncthreads();

    int tx = tid & 7;               // cols 4tx..4tx+3
    int ty = tid >> 3;              // rows 4ty..4ty+3
    const float* xr = xs + 4 * ty * FH;
    const ulonglong2* Wp = (const ulonglong2*)Ws;  // 8 per k-row (32 cols)
    unsigned long long acc[4][2] = {};

    #define G2_STEP(KK, CMP)                                               \
        do {                                                               \
            ulonglong2 w = Wp[(k + KK) * 8 + tx];                          \
            unsigned long long aa;                                         \
            BCAST2(aa, a0.CMP); FMA2(acc[0][0], aa, w.x); FMA2(acc[0][1], aa, w.y); \
            BCAST2(aa, a1.CMP); FMA2(acc[1][0], aa, w.x); FMA2(acc[1][1], aa, w.y); \
            BCAST2(aa, a2.CMP); FMA2(acc[2][0], aa, w.x); FMA2(acc[2][1], aa, w.y); \
            BCAST2(aa, a3.CMP); FMA2(acc[3][0], aa, w.x); FMA2(acc[3][1], aa, w.y); \
        } while (0)

    #pragma unroll 4
    for (int k = 0; k < FH; k += 4) {
        float4 a0 = *(const float4*)(xr + 0 * FH + k);
        float4 a1 = *(const float4*)(xr + 1 * FH + k);
        float4 a2 = *(const float4*)(xr + 2 * FH + k);
        float4 a3 = *(const float4*)(xr + 3 * FH + k);
        G2_STEP(0, x); G2_STEP(1, y); G2_STEP(2, z); G2_STEP(3, w);
    }
    #undef G2_STEP

    uint2* h3v = (uint2*)g_h3h;                    // 8 uint2 per row
    #pragma unroll
    for (int j = 0; j < 4; j++) {
        int row = row0 + 4 * ty + j;
        if (row < NN) {
            float2 f01 = *(float2*)&acc[j][0];
            float2 f23 = *(float2*)&acc[j][1];
            __half2 h01 = __float22half2_rn(f01);
            __half2 h23 = __float22half2_rn(f23);
            uint2 u;
            u.x = *(unsigned*)&h01;
            u.y = *(unsigned*)&h23;
            h3v[(size_t)row * 8 + tx] = u;
        }
    }
}

// Aggregation layer 2 (+ self-loop + bias): 8 lanes per dst node, each lane
// gathers 4 fp16 features per edge; fp32 accumulate; fp32 store to d_out.
__global__ __launch_bounds__(256) void k_agg2(float* __restrict__ out,
                                              const float* __restrict__ b2) {
    int gid = blockIdx.x * 256 + threadIdx.x;
    int node = gid >> 3;
    int lane = threadIdx.x & 7;
    if (node >= NN) return;
    int off = g_off[node];
    int n   = g_off[node + 1] - off;
    const uint2* h3v = (const uint2*)g_h3h;    // 8 uint2 per row
    float4 acc = make_float4(0.f, 0.f, 0.f, 0.f);

    #define AGG2_TERM(u, nm)                                              \
        do {                                                              \
            __half2 hl = *(__half2*)&(u).x;                               \
            __half2 hh = *(__half2*)&(u).y;                               \
            float2 pl = __half22float2(hl);                               \
            float2 ph = __half22float2(hh);                               \
            acc.x = fmaf(pl.x, nm, acc.x); acc.y = fmaf(pl.y, nm, acc.y); \
            acc.z = fmaf(ph.x, nm, acc.z); acc.w = fmaf(ph.y, nm, acc.w); \
        } while (0)

    int i = 0;
    for (; i + 1 < n; i += 2) {
        int2 e0 = g_edge[off + i];
        int2 e1 = g_edge[off + i + 1];
        uint2 u0 = h3v[(size_t)e0.x * 8 + lane];
        uint2 u1 = h3v[(size_t)e1.x * 8 + lane];
        float n0 = __int_as_float(e0.y), n1 = __int_as_float(e1.y);
        AGG2_TERM(u0, n0);
        AGG2_TERM(u1, n1);
    }
    if (i < n) {
        int2 e0 = g_edge[off + i];
        uint2 u0 = h3v[(size_t)e0.x * 8 + lane];
        float n0 = __int_as_float(e0.y);
        AGG2_TERM(u0, n0);
    }
    {   // self-loop
        float di = g_dinv[node];
        float w = di * di;
        uint2 us = h3v[(size_t)node * 8 + lane];
        AGG2_TERM(us, w);
    }
    #undef AGG2_TERM

    float4 bb = ((const float4*)b2)[lane];
    acc.x += bb.x;
    acc.y += bb.y;
    acc.z += bb.z;
    acc.w += bb.w;
    ((float4*)out)[(size_t)node * 8 + lane] = acc;
}

// ---------------------------------------------------------------------------
namespace {
struct Ctx {
    cudaStream_t s2;
    cudaEvent_t e_fork, e_join;
    Ctx() {
        cudaStreamCreateWithFlags(&s2, cudaStreamNonBlocking);
        cudaEventCreateWithFlags(&e_fork, cudaEventDisableTiming);
        cudaEventCreateWithFlags(&e_join, cudaEventDisableTiming);
    }
};
}

extern "C" void kernel_launch(void* const* d_in, const int* in_sizes, int n_in,
                              void* d_out, int out_size) {
    static Ctx ctx;   // created on first (uncaptured) correctness call

    const float* x  = (const float*)d_in[0];
    const int*   ei = (const int*)d_in[1];     // int32 (JAX x64 disabled)
    const float* W1 = (const float*)d_in[2];
    const float* b1 = (const float*)d_in[3];
    const float* W2 = (const float*)d_in[4];
    const float* b2 = (const float*)d_in[5];
    float* out = (float*)d_out;

    const int E = in_sizes[1] / 2;

    // Fork: graph preprocessing on ctx.s2 concurrently with GEMM1.
    cudaEventRecord(ctx.e_fork, 0);
    cudaStreamWaitEvent(ctx.s2, ctx.e_fork, 0);

    k_deg<<<(E + 255) / 256, 256, 0, ctx.s2>>>(ei, E);
    k_scan<<<NSCAN_BLK, 512, 0, ctx.s2>>>();
    k_scatter<<<(E + 255) / 256, 256, 0, ctx.s2>>>(ei, E);
    cudaEventRecord(ctx.e_join, ctx.s2);

    k_gemm1<<<(NN + 63) / 64, 256>>>(x, W1);

    // Join: aggregation needs both h1 and the grouped edge list.
    cudaStreamWaitEvent(0, ctx.e_join, 0);

    k_agg1<<<(unsigned)(((long)NN * 16 + 255) / 256), 256>>>(b1);
    k_gemm2<<<(NN + 127) / 128, 256>>>(W2);
    k_agg2<<<(unsigned)(((long)NN * 8 + 255) / 256), 256>>>(out, b2);
}

// round 14
// speedup vs baseline: 1.1358x; 1.0054x over previous
#include <cuda_runtime.h>
#include <cuda_fp16.h>
#include <mma.h>
#include <cstdint>

using namespace nvcuda;

#define NN 100000
#define F1 128
#define FH 64
#define FO 32
#define EMAX 1600000
#define NSCAN_BLK 196            // ceil(100000/512)

// Scratch (no allocations allowed).
__device__ int   g_deg[NN];                     // zero at load; re-zeroed by k_scatter
__device__ int   g_cur[NN];
__device__ int   g_off[NN + 1];
__device__ unsigned long long g_lb[NSCAN_BLK];  // lookback: (flag<<32)|value; zeroed by k_scatter
__device__ float g_dinv[NN];
__device__ int2  g_edge[EMAX];                  // (src, norm) grouped by dst
__device__ __half g_h1h[(size_t)NN * FH];       // x @ W1, fp16 (gather payload)
__device__ float  g_a1[(size_t)NN * FH];        // layer-1 activations (post ReLU), fp32
__device__ __half g_h3h[(size_t)NN * FO];       // a1 @ W2, fp16 (gather payload)

#define FMA2(acc, aa, ww) \
    asm("fma.rn.f32x2 %0, %1, %2, %0;" : "+l"(acc) : "l"(aa), "l"(ww))
#define BCAST2(aa, a) \
    asm("mov.b64 %0, {%1, %1};" : "=l"(aa) : "f"(a))

// ---------------------------------------------------------------------------
__global__ void k_deg(const int* __restrict__ ei, int E) {
    int i = blockIdx.x * blockDim.x + threadIdx.x;
    if (i < E) atomicAdd(&g_deg[ei[E + i]], 1);
}

// Single-pass decoupled-lookback exclusive scan of g_deg -> g_off,
// fused with cursor reset and dinv computation.
__global__ __launch_bounds__(512) void k_scan() {
    __shared__ int sh[512];
    __shared__ int s_prev;
    int t = threadIdx.x;
    int b = blockIdx.x;
    int i = b * 512 + t;
    int deg = (i < NN) ? g_deg[i] : 0;
    sh[t] = deg;
    for (int d = 1; d < 512; d <<= 1) {
        __syncthreads();
        int u = (t >= d) ? sh[t - d] : 0;
        __syncthreads();
        sh[t] += u;
    }
    __syncthreads();
    int agg = sh[511];

    if (t == 0) {
        if (b == 0) atomicExch(&g_lb[0], (2ULL << 32) | (unsigned)agg);
        else        atomicExch(&g_lb[b], (1ULL << 32) | (unsigned)agg);
    }

    if (b > 0 && t < 32) {                 // warp-parallel lookback
        int excl = 0;
        int hi = b - 1;
        for (;;) {
            int idx = hi - t;
            unsigned long long w = 0;
            if (idx >= 0) w = *(volatile unsigned long long*)&g_lb[idx];
            unsigned f = (idx >= 0) ? (unsigned)(w >> 32) : 2u;
            if (__ballot_sync(0xffffffffu, f == 0u)) continue;   // retry window
            int v = (int)(unsigned)(w & 0xffffffffULL);
            unsigned haspfx = __ballot_sync(0xffffffffu, f == 2u && idx >= 0);
            if (haspfx) {
                int first = __ffs(haspfx) - 1;   // nearest lane with a prefix
                int contrib = (idx >= 0 && t <= first) ? v : 0;
                #pragma unroll
                for (int o = 16; o; o >>= 1) contrib += __shfl_down_sync(0xffffffffu, contrib, o);
                excl += __shfl_sync(0xffffffffu, contrib, 0);
                break;
            } else {
                int contrib = (idx >= 0) ? v : 0;
                #pragma unroll
                for (int o = 16; o; o >>= 1) contrib += __shfl_down_sync(0xffffffffu, contrib, o);
                excl += __shfl_sync(0xffffffffu, contrib, 0);
                hi -= 32;
            }
        }
        if (t == 0) {
            s_prev = excl;
            atomicExch(&g_lb[b], (2ULL << 32) | (unsigned)(excl + agg));
        }
    } else if (b == 0 && t == 0) {
        s_prev = 0;
    }
    __syncthreads();

    if (i < NN) {
        g_off[i] = s_prev + sh[t] - deg;   // exclusive
        g_cur[i] = 0;
        g_dinv[i] = rsqrtf((float)deg + 1.0f);   // +1 self-loop
    }
    if (b == NSCAN_BLK - 1 && t == 511) g_off[NN] = s_prev + sh[511];
}

// Scatter edges into destination-grouped order; also reset deg/lookback state
// so the next call (graph replay) starts from the module-load invariant.
__global__ void k_scatter(const int* __restrict__ ei, int E) {
    int e = blockIdx.x * blockDim.x + threadIdx.x;
    if (e >= E) return;
    int s = ei[e];
    int d = ei[E + e];
    float norm = g_dinv[s] * g_dinv[d];
    int pos = g_off[d] + atomicAdd(&g_cur[d], 1);
    g_edge[pos] = make_int2(s, __float_as_int(norm));
    if (e < NN) g_deg[e] = 0;
    if (e < NSCAN_BLK) g_lb[e] = 0ULL;
}

// ---------------------------------------------------------------------------
// GEMM1 (tensor cores): h1[NN,64] = x[NN,128] @ W1[128,64], fp16 in / fp32 acc.
// 64 rows/block, 256 threads = 8 warps; each warp owns a 16x32 output tile.
// Row strides padded to odd 16B-chunk counts (17/9) -> conflict-free ldmatrix.
#define XS_LD 136   // halfs per x-tile row   (272 B = 17 chunks)
#define WS_LD 72    // halfs per W-tile row   (144 B = 9 chunks)
#define OS_LD 72    // floats per out-tile row

__global__ __launch_bounds__(256) void k_gemm1(const float* __restrict__ x,
                                               const float* __restrict__ W) {
    __shared__ __align__(16) char smbuf[64 * XS_LD * 2 + F1 * WS_LD * 2]; // 35840 B
    __half* xsh = (__half*)smbuf;
    __half* Wsh = (__half*)(smbuf + 64 * XS_LD * 2);
    float*  osh = (float*)smbuf;           // aliases xsh/Wsh AFTER the mainloop

    int tid = threadIdx.x;
    int row0 = blockIdx.x * 64;

    // Load W1 -> fp16 smem: 128x64, 2048 float4s.
    const float4* W4 = (const float4*)W;
    for (int i = tid; i < F1 * FH / 4; i += 256) {
        int k = i >> 4, c4 = i & 15;
        float4 v = W4[i];
        __half2 h01 = __float22half2_rn(make_float2(v.x, v.y));
        __half2 h23 = __float22half2_rn(make_float2(v.z, v.w));
        uint2 u; u.x = *(unsigned*)&h01; u.y = *(unsigned*)&h23;
        *(uint2*)&Wsh[k * WS_LD + c4 * 4] = u;
    }
    // Load x tile -> fp16 smem: 64x128, 2048 float4s.
    const float4* x4 = (const float4*)x;
    for (int i = tid; i < 64 * F1 / 4; i += 256) {
        int r = i >> 5, c4 = i & 31;
        int row = row0 + r;
        float4 v = (row < NN) ? x4[(size_t)row * 32 + c4]
                              : make_float4(0.f, 0.f, 0.f, 0.f);
        __half2 h01 = __float22half2_rn(make_float2(v.x, v.y));
        __half2 h23 = __float22half2_rn(make_float2(v.z, v.w));
        uint2 u; u.x = *(unsigned*)&h01; u.y = *(unsigned*)&h23;
        *(uint2*)&xsh[r * XS_LD + c4 * 4] = u;
    }
    __syncthreads();

    int warp = tid >> 5;
    int wr = warp >> 1;            // 0..3 : rows wr*16
    int wc = warp & 1;             // 0..1 : cols wc*32

    wmma::fragment<wmma::matrix_a, 16, 16, 16, __half, wmma::row_major> af;
    wmma::fragment<wmma::matrix_b, 16, 16, 16, __half, wmma::row_major> bf0, bf1;
    wmma::fragment<wmma::accumulator, 16, 16, 16, float> c0, c1;
    wmma::fill_fragment(c0, 0.f);
    wmma::fill_fragment(c1, 0.f);

    #pragma unroll
    for (int k = 0; k < 8; k++) {
        wmma::load_matrix_sync(af, xsh + wr * 16 * XS_LD + k * 16, XS_LD);
        wmma::load_matrix_sync(bf0, Wsh + k * 16 * WS_LD + wc * 32, WS_LD);
        wmma::load_matrix_sync(bf1, Wsh + k * 16 * WS_LD + wc * 32 + 16, WS_LD);
        wmma::mma_sync(c0, af, bf0, c0);
        wmma::mma_sync(c1, af, bf1, c1);
    }

    __syncthreads();   // xsh/Wsh dead; osh aliases them
    wmma::store_matrix_sync(osh + wr * 16 * OS_LD + wc * 32,      c0, OS_LD, wmma::mem_row_major);
    wmma::store_matrix_sync(osh + wr * 16 * OS_LD + wc * 32 + 16, c1, OS_LD, wmma::mem_row_major);
    __syncthreads();

    // Convert fp32 smem tile -> fp16 global (uint2 = 4 halfs per write).
    uint2* h1v = (uint2*)g_h1h;            // 16 uint2 per row
    for (int i = tid; i < 64 * 16; i += 256) {
        int r = i >> 4, c4 = i & 15;
        int row = row0 + r;
        if (row < NN) {
            float4 v = *(float4*)&osh[r * OS_LD + c4 * 4];
            __half2 h01 = __float22half2_rn(make_float2(v.x, v.y));
            __half2 h23 = __float22half2_rn(make_float2(v.z, v.w));
            uint2 u; u.x = *(unsigned*)&h01; u.y = *(unsigned*)&h23;
            h1v[(size_t)row * 16 + c4] = u;
        }
    }
}

// Aggregation layer 1 (+ self-loop + bias + ReLU): 16 lanes per dst node,
// each lane gathers 4 fp16 features (uint2 = 8B) per edge; fp32 accumulate.
__global__ __launch_bounds__(256) void k_agg1(const float* __restrict__ b1) {
    int gid = blockIdx.x * 256 + threadIdx.x;
    int node = gid >> 4;
    int lane = threadIdx.x & 15;
    if (node >= NN) return;
    int off = g_off[node];
    int n   = g_off[node + 1] - off;
    const uint2* h1v = (const uint2*)g_h1h;    // 16 uint2 per row
    float4 acc = make_float4(0.f, 0.f, 0.f, 0.f);

    #define AGG1_TERM(u, nm)                                              \
        do {                                                              \
            __half2 hl = *(__half2*)&(u).x;                               \
            __half2 hh = *(__half2*)&(u).y;                               \
            float2 pl = __half22float2(hl);                               \
            float2 ph = __half22float2(hh);                               \
            acc.x = fmaf(pl.x, nm, acc.x); acc.y = fmaf(pl.y, nm, acc.y); \
            acc.z = fmaf(ph.x, nm, acc.z); acc.w = fmaf(ph.y, nm, acc.w); \
        } while (0)

    int i = 0;
    for (; i + 1 < n; i += 2) {
        int2 e0 = g_edge[off + i];
        int2 e1 = g_edge[off + i + 1];
        uint2 u0 = h1v[(size_t)e0.x * 16 + lane];
        uint2 u1 = h1v[(size_t)e1.x * 16 + lane];
        float n0 = __int_as_float(e0.y), n1 = __int_as_float(e1.y);
        AGG1_TERM(u0, n0);
        AGG1_TERM(u1, n1);
    }
    if (i < n) {
        int2 e0 = g_edge[off + i];
        uint2 u0 = h1v[(size_t)e0.x * 16 + lane];
        float n0 = __int_as_float(e0.y);
        AGG1_TERM(u0, n0);
    }
    {   // self-loop
        float di = g_dinv[node];
        float w = di * di;
        uint2 us = h1v[(size_t)node * 16 + lane];
        AGG1_TERM(us, w);
    }
    #undef AGG1_TERM

    float4 bb = ((const float4*)b1)[lane];
    acc.x = fmaxf(acc.x + bb.x, 0.f);
    acc.y = fmaxf(acc.y + bb.y, 0.f);
    acc.z = fmaxf(acc.z + bb.z, 0.f);
    acc.w = fmaxf(acc.w + bb.w, 0.f);
    ((float4*)g_a1)[(size_t)node * 16 + lane] = acc;
}

// ---------------------------------------------------------------------------
// GEMM2: h3[NN,32] = a1[NN,64] @ W2[64,32].
// 128 rows/block, 256 threads, 4 rows x 4 cols per thread, FFMA2 math,
// K chunked by 4 with float4 activation loads. Output stored as fp16.
__global__ __launch_bounds__(256) void k_gemm2(const float* __restrict__ W) {
    __shared__ float Ws[FH * FO];    // 8 KB
    __shared__ float xs[128 * FH];   // 32 KB
    int tid = threadIdx.x;
    float4* Ws4 = (float4*)Ws;
    const float4* W4 = (const float4*)W;
    for (int i = tid; i < FH * FO / 4; i += 256) Ws4[i] = W4[i];
    int row0 = blockIdx.x * 128;
    const float4* x4 = (const float4*)g_a1;
    float4* xs4 = (float4*)xs;
    for (int i = tid; i < 128 * FH / 4; i += 256) {
        int row = row0 + (i >> 4);                 // 16 float4 per row
        xs4[i] = (row < NN) ? x4[(size_t)row * 16 + (i & 15)]
                            : make_float4(0.f, 0.f, 0.f, 0.f);
    }
    __syncthreads();

    int tx = tid & 7;               // cols 4tx..4tx+3
    int ty = tid >> 3;              // rows 4ty..4ty+3
    const float* xr = xs + 4 * ty * FH;
    const ulonglong2* Wp = (const ulonglong2*)Ws;  // 8 per k-row (32 cols)
    unsigned long long acc[4][2] = {};

    #define G2_STEP(KK, CMP)                                               \
        do {                                                               \
            ulonglong2 w = Wp[(k + KK) * 8 + tx];                          \
            unsigned long long aa;                                         \
            BCAST2(aa, a0.CMP); FMA2(acc[0][0], aa, w.x); FMA2(acc[0][1], aa, w.y); \
            BCAST2(aa, a1.CMP); FMA2(acc[1][0], aa, w.x); FMA2(acc[1][1], aa, w.y); \
            BCAST2(aa, a2.CMP); FMA2(acc[2][0], aa, w.x); FMA2(acc[2][1], aa, w.y); \
            BCAST2(aa, a3.CMP); FMA2(acc[3][0], aa, w.x); FMA2(acc[3][1], aa, w.y); \
        } while (0)

    #pragma unroll 4
    for (int k = 0; k < FH; k += 4) {
        float4 a0 = *(const float4*)(xr + 0 * FH + k);
        float4 a1 = *(const float4*)(xr + 1 * FH + k);
        float4 a2 = *(const float4*)(xr + 2 * FH + k);
        float4 a3 = *(const float4*)(xr + 3 * FH + k);
        G2_STEP(0, x); G2_STEP(1, y); G2_STEP(2, z); G2_STEP(3, w);
    }
    #undef G2_STEP

    uint2* h3v = (uint2*)g_h3h;                    // 8 uint2 per row
    #pragma unroll
    for (int j = 0; j < 4; j++) {
        int row = row0 + 4 * ty + j;
        if (row < NN) {
            float2 f01 = *(float2*)&acc[j][0];
            float2 f23 = *(float2*)&acc[j][1];
            __half2 h01 = __float22half2_rn(f01);
            __half2 h23 = __float22half2_rn(f23);
            uint2 u;
            u.x = *(unsigned*)&h01;
            u.y = *(unsigned*)&h23;
            h3v[(size_t)row * 8 + tx] = u;
        }
    }
}

// Aggregation layer 2 (+ self-loop + bias): 8 lanes per dst node, each lane
// gathers 4 fp16 features per edge; fp32 accumulate; fp32 store to d_out.
__global__ __launch_bounds__(256) void k_agg2(float* __restrict__ out,
                                              const float* __restrict__ b2) {
    int gid = blockIdx.x * 256 + threadIdx.x;
    int node = gid >> 3;
    int lane = threadIdx.x & 7;
    if (node >= NN) return;
    int off = g_off[node];
    int n   = g_off[node + 1] - off;
    const uint2* h3v = (const uint2*)g_h3h;    // 8 uint2 per row
    float4 acc = make_float4(0.f, 0.f, 0.f, 0.f);

    #define AGG2_TERM(u, nm)                                              \
        do {                                                              \
            __half2 hl = *(__half2*)&(u).x;                               \
            __half2 hh = *(__half2*)&(u).y;                               \
            float2 pl = __half22float2(hl);                               \
            float2 ph = __half22float2(hh);                               \
            acc.x = fmaf(pl.x, nm, acc.x); acc.y = fmaf(pl.y, nm, acc.y); \
            acc.z = fmaf(ph.x, nm, acc.z); acc.w = fmaf(ph.y, nm, acc.w); \
        } while (0)

    int i = 0;
    for (; i + 1 < n; i += 2) {
        int2 e0 = g_edge[off + i];
        int2 e1 = g_edge[off + i + 1];
        uint2 u0 = h3v[(size_t)e0.x * 8 + lane];
        uint2 u1 = h3v[(size_t)e1.x * 8 + lane];
        float n0 = __int_as_float(e0.y), n1 = __int_as_float(e1.y);
        AGG2_TERM(u0, n0);
        AGG2_TERM(u1, n1);
    }
    if (i < n) {
        int2 e0 = g_edge[off + i];
        uint2 u0 = h3v[(size_t)e0.x * 8 + lane];
        float n0 = __int_as_float(e0.y);
        AGG2_TERM(u0, n0);
    }
    {   // self-loop
        float di = g_dinv[node];
        float w = di * di;
        uint2 us = h3v[(size_t)node * 8 + lane];
        AGG2_TERM(us, w);
    }
    #undef AGG2_TERM

    float4 bb = ((const float4*)b2)[lane];
    acc.x += bb.x;
    acc.y += bb.y;
    acc.z += bb.z;
    acc.w += bb.w;
    ((float4*)out)[(size_t)node * 8 + lane] = acc;
}

// ---------------------------------------------------------------------------
namespace {
struct Ctx {
    cudaStream_t s2;
    cudaEvent_t e_fork, e_join;
    Ctx() {
        cudaStreamCreateWithFlags(&s2, cudaStreamNonBlocking);
        cudaEventCreateWithFlags(&e_fork, cudaEventDisableTiming);
        cudaEventCreateWithFlags(&e_join, cudaEventDisableTiming);
    }
};
}

extern "C" void kernel_launch(void* const* d_in, const int* in_sizes, int n_in,
                              void* d_out, int out_size) {
    static Ctx ctx;   // created on first (uncaptured) correctness call

    const float* x  = (const float*)d_in[0];
    const int*   ei = (const int*)d_in[1];     // int32 (JAX x64 disabled)
    const float* W1 = (const float*)d_in[2];
    const float* b1 = (const float*)d_in[3];
    const float* W2 = (const float*)d_in[4];
    const float* b2 = (const float*)d_in[5];
    float* out = (float*)d_out;

    const int E = in_sizes[1] / 2;

    // Fork: graph preprocessing on ctx.s2 concurrently with GEMM1.
    cudaEventRecord(ctx.e_fork, 0);
    cudaStreamWaitEvent(ctx.s2, ctx.e_fork, 0);

    k_deg<<<(E + 255) / 256, 256, 0, ctx.s2>>>(ei, E);
    k_scan<<<NSCAN_BLK, 512, 0, ctx.s2>>>();
    k_scatter<<<(E + 255) / 256, 256, 0, ctx.s2>>>(ei, E);
    cudaEventRecord(ctx.e_join, ctx.s2);

    k_gemm1<<<(NN + 63) / 64, 256>>>(x, W1);

    // Join: aggregation needs both h1 and the grouped edge list.
    cudaStreamWaitEvent(0, ctx.e_join, 0);

    k_agg1<<<(unsigned)(((long)NN * 16 + 255) / 256), 256>>>(b1);
    k_gemm2<<<(NN + 127) / 128, 256>>>(W2);
    k_agg2<<<(unsigned)(((long)NN * 8 + 255) / 256), 256>>>(out, b2);
}

// round 15
// speedup vs baseline: 1.2335x; 1.0860x over previous
#include <cuda_runtime.h>
#include <cuda_fp16.h>
#include <mma.h>
#include <cstdint>

using namespace nvcuda;

#define NN 100000
#define F1 128
#define FH 64
#define FO 32
#define EMAX 1600000
#define NSCAN_BLK 196            // ceil(100000/512)

// Scratch (no allocations allowed).
__device__ int   g_deg[NN];                     // zero at load; re-zeroed by k_scatter
__device__ int   g_cur[NN];
__device__ int   g_off[NN + 1];
__device__ unsigned long long g_lb[NSCAN_BLK];  // lookback: (flag<<32)|value; zeroed by k_scatter
__device__ float g_dinv[NN];
__device__ int2  g_edge[EMAX];                  // (src, norm) grouped by dst
__device__ __half g_h1h[(size_t)NN * FH];       // x @ W1, fp16 (gather payload)
__device__ __half g_a1h[(size_t)NN * FH];       // layer-1 activations (post ReLU), fp16
__device__ __half g_h3h[(size_t)NN * FO];       // a1 @ W2, fp16 (gather payload)

// ---------------------------------------------------------------------------
__global__ void k_deg(const int* __restrict__ ei, int E) {
    int i = blockIdx.x * blockDim.x + threadIdx.x;
    if (i < E) atomicAdd(&g_deg[ei[E + i]], 1);
}

// Single-pass decoupled-lookback exclusive scan of g_deg -> g_off,
// fused with cursor reset and dinv computation.
__global__ __launch_bounds__(512) void k_scan() {
    __shared__ int sh[512];
    __shared__ int s_prev;
    int t = threadIdx.x;
    int b = blockIdx.x;
    int i = b * 512 + t;
    int deg = (i < NN) ? g_deg[i] : 0;
    sh[t] = deg;
    for (int d = 1; d < 512; d <<= 1) {
        __syncthreads();
        int u = (t >= d) ? sh[t - d] : 0;
        __syncthreads();
        sh[t] += u;
    }
    __syncthreads();
    int agg = sh[511];

    if (t == 0) {
        if (b == 0) atomicExch(&g_lb[0], (2ULL << 32) | (unsigned)agg);
        else        atomicExch(&g_lb[b], (1ULL << 32) | (unsigned)agg);
    }

    if (b > 0 && t < 32) {                 // warp-parallel lookback
        int excl = 0;
        int hi = b - 1;
        for (;;) {
            int idx = hi - t;
            unsigned long long w = 0;
            if (idx >= 0) w = *(volatile unsigned long long*)&g_lb[idx];
            unsigned f = (idx >= 0) ? (unsigned)(w >> 32) : 2u;
            if (__ballot_sync(0xffffffffu, f == 0u)) continue;   // retry window
            int v = (int)(unsigned)(w & 0xffffffffULL);
            unsigned haspfx = __ballot_sync(0xffffffffu, f == 2u && idx >= 0);
            if (haspfx) {
                int first = __ffs(haspfx) - 1;   // nearest lane with a prefix
                int contrib = (idx >= 0 && t <= first) ? v : 0;
                #pragma unroll
                for (int o = 16; o; o >>= 1) contrib += __shfl_down_sync(0xffffffffu, contrib, o);
                excl += __shfl_sync(0xffffffffu, contrib, 0);
                break;
            } else {
                int contrib = (idx >= 0) ? v : 0;
                #pragma unroll
                for (int o = 16; o; o >>= 1) contrib += __shfl_down_sync(0xffffffffu, contrib, o);
                excl += __shfl_sync(0xffffffffu, contrib, 0);
                hi -= 32;
            }
        }
        if (t == 0) {
            s_prev = excl;
            atomicExch(&g_lb[b], (2ULL << 32) | (unsigned)(excl + agg));
        }
    } else if (b == 0 && t == 0) {
        s_prev = 0;
    }
    __syncthreads();

    if (i < NN) {
        g_off[i] = s_prev + sh[t] - deg;   // exclusive
        g_cur[i] = 0;
        g_dinv[i] = rsqrtf((float)deg + 1.0f);   // +1 self-loop
    }
    if (b == NSCAN_BLK - 1 && t == 511) g_off[NN] = s_prev + sh[511];
}

// Scatter edges into destination-grouped order; also reset deg/lookback state
// so the next call (graph replay) starts from the module-load invariant.
__global__ void k_scatter(const int* __restrict__ ei, int E) {
    int e = blockIdx.x * blockDim.x + threadIdx.x;
    if (e >= E) return;
    int s = ei[e];
    int d = ei[E + e];
    float norm = g_dinv[s] * g_dinv[d];
    int pos = g_off[d] + atomicAdd(&g_cur[d], 1);
    g_edge[pos] = make_int2(s, __float_as_int(norm));
    if (e < NN) g_deg[e] = 0;
    if (e < NSCAN_BLK) g_lb[e] = 0ULL;
}

// ---------------------------------------------------------------------------
// GEMM1 (tensor cores): h1[NN,64] = x[NN,128] @ W1[128,64], fp16 in / fp32 acc.
// 64 rows/block, 256 threads = 8 warps; each warp owns a 16x32 output tile.
#define XS_LD 136   // halfs per x-tile row   (272 B = 17 chunks)
#define WS_LD 72    // halfs per W-tile row   (144 B = 9 chunks)
#define OS_LD 72    // floats per out-tile row

__global__ __launch_bounds__(256) void k_gemm1(const float* __restrict__ x,
                                               const float* __restrict__ W) {
    __shared__ __align__(16) char smbuf[64 * XS_LD * 2 + F1 * WS_LD * 2]; // 35840 B
    __half* xsh = (__half*)smbuf;
    __half* Wsh = (__half*)(smbuf + 64 * XS_LD * 2);
    float*  osh = (float*)smbuf;           // aliases xsh/Wsh AFTER the mainloop

    int tid = threadIdx.x;
    int row0 = blockIdx.x * 64;

    const float4* W4 = (const float4*)W;
    for (int i = tid; i < F1 * FH / 4; i += 256) {
        int k = i >> 4, c4 = i & 15;
        float4 v = W4[i];
        __half2 h01 = __float22half2_rn(make_float2(v.x, v.y));
        __half2 h23 = __float22half2_rn(make_float2(v.z, v.w));
        uint2 u; u.x = *(unsigned*)&h01; u.y = *(unsigned*)&h23;
        *(uint2*)&Wsh[k * WS_LD + c4 * 4] = u;
    }
    const float4* x4 = (const float4*)x;
    for (int i = tid; i < 64 * F1 / 4; i += 256) {
        int r = i >> 5, c4 = i & 31;
        int row = row0 + r;
        float4 v = (row < NN) ? x4[(size_t)row * 32 + c4]
                              : make_float4(0.f, 0.f, 0.f, 0.f);
        __half2 h01 = __float22half2_rn(make_float2(v.x, v.y));
        __half2 h23 = __float22half2_rn(make_float2(v.z, v.w));
        uint2 u; u.x = *(unsigned*)&h01; u.y = *(unsigned*)&h23;
        *(uint2*)&xsh[r * XS_LD + c4 * 4] = u;
    }
    __syncthreads();

    int warp = tid >> 5;
    int wr = warp >> 1;            // 0..3 : rows wr*16
    int wc = warp & 1;             // 0..1 : cols wc*32

    wmma::fragment<wmma::matrix_a, 16, 16, 16, __half, wmma::row_major> af;
    wmma::fragment<wmma::matrix_b, 16, 16, 16, __half, wmma::row_major> bf0, bf1;
    wmma::fragment<wmma::accumulator, 16, 16, 16, float> c0, c1;
    wmma::fill_fragment(c0, 0.f);
    wmma::fill_fragment(c1, 0.f);

    #pragma unroll
    for (int k = 0; k < 8; k++) {
        wmma::load_matrix_sync(af, xsh + wr * 16 * XS_LD + k * 16, XS_LD);
        wmma::load_matrix_sync(bf0, Wsh + k * 16 * WS_LD + wc * 32, WS_LD);
        wmma::load_matrix_sync(bf1, Wsh + k * 16 * WS_LD + wc * 32 + 16, WS_LD);
        wmma::mma_sync(c0, af, bf0, c0);
        wmma::mma_sync(c1, af, bf1, c1);
    }

    __syncthreads();   // xsh/Wsh dead; osh aliases them
    wmma::store_matrix_sync(osh + wr * 16 * OS_LD + wc * 32,      c0, OS_LD, wmma::mem_row_major);
    wmma::store_matrix_sync(osh + wr * 16 * OS_LD + wc * 32 + 16, c1, OS_LD, wmma::mem_row_major);
    __syncthreads();

    uint2* h1v = (uint2*)g_h1h;            // 16 uint2 per row
    for (int i = tid; i < 64 * 16; i += 256) {
        int r = i >> 4, c4 = i & 15;
        int row = row0 + r;
        if (row < NN) {
            float4 v = *(float4*)&osh[r * OS_LD + c4 * 4];
            __half2 h01 = __float22half2_rn(make_float2(v.x, v.y));
            __half2 h23 = __float22half2_rn(make_float2(v.z, v.w));
            uint2 u; u.x = *(unsigned*)&h01; u.y = *(unsigned*)&h23;
            h1v[(size_t)row * 16 + c4] = u;
        }
    }
}

// Aggregation layer 1 (+ self-loop + bias + ReLU): 16 lanes per dst node,
// each lane gathers 4 fp16 features per edge; fp32 accumulate; fp16 store.
__global__ __launch_bounds__(256) void k_agg1(const float* __restrict__ b1) {
    int gid = blockIdx.x * 256 + threadIdx.x;
    int node = gid >> 4;
    int lane = threadIdx.x & 15;
    if (node >= NN) return;
    int off = g_off[node];
    int n   = g_off[node + 1] - off;
    const uint2* h1v = (const uint2*)g_h1h;    // 16 uint2 per row
    float4 acc = make_float4(0.f, 0.f, 0.f, 0.f);

    #define AGG1_TERM(u, nm)                                              \
        do {                                                              \
            __half2 hl = *(__half2*)&(u).x;                               \
            __half2 hh = *(__half2*)&(u).y;                               \
            float2 pl = __half22float2(hl);                               \
            float2 ph = __half22float2(hh);                               \
            acc.x = fmaf(pl.x, nm, acc.x); acc.y = fmaf(pl.y, nm, acc.y); \
            acc.z = fmaf(ph.x, nm, acc.z); acc.w = fmaf(ph.y, nm, acc.w); \
        } while (0)

    int i = 0;
    for (; i + 1 < n; i += 2) {
        int2 e0 = g_edge[off + i];
        int2 e1 = g_edge[off + i + 1];
        uint2 u0 = h1v[(size_t)e0.x * 16 + lane];
        uint2 u1 = h1v[(size_t)e1.x * 16 + lane];
        float n0 = __int_as_float(e0.y), n1 = __int_as_float(e1.y);
        AGG1_TERM(u0, n0);
        AGG1_TERM(u1, n1);
    }
    if (i < n) {
        int2 e0 = g_edge[off + i];
        uint2 u0 = h1v[(size_t)e0.x * 16 + lane];
        float n0 = __int_as_float(e0.y);
        AGG1_TERM(u0, n0);
    }
    {   // self-loop
        float di = g_dinv[node];
        float w = di * di;
        uint2 us = h1v[(size_t)node * 16 + lane];
        AGG1_TERM(us, w);
    }
    #undef AGG1_TERM

    float4 bb = ((const float4*)b1)[lane];
    acc.x = fmaxf(acc.x + bb.x, 0.f);
    acc.y = fmaxf(acc.y + bb.y, 0.f);
    acc.z = fmaxf(acc.z + bb.z, 0.f);
    acc.w = fmaxf(acc.w + bb.w, 0.f);
    __half2 o01 = __float22half2_rn(make_float2(acc.x, acc.y));
    __half2 o23 = __float22half2_rn(make_float2(acc.z, acc.w));
    uint2 ou; ou.x = *(unsigned*)&o01; ou.y = *(unsigned*)&o23;
    ((uint2*)g_a1h)[(size_t)node * 16 + lane] = ou;
}

// ---------------------------------------------------------------------------
// GEMM2 (tensor cores): h3[NN,32] = a1[NN,64] @ W2[64,32], fp16 in / fp32 acc.
// 128 rows/block, 256 threads = 8 warps; each warp owns a 16x32 output tile.
#define XS2_LD 72   // halfs per a1-tile row  (144 B = 9 chunks)
#define WS2_LD 40   // halfs per W2-tile row  (80 B = 5 chunks)
#define OS2_LD 40   // floats per out-tile row

__global__ __launch_bounds__(256) void k_gemm2(const float* __restrict__ W) {
    __shared__ __align__(16) char smbuf[128 * XS2_LD * 2 + FH * WS2_LD * 2]; // 23552 B
    __half* xsh = (__half*)smbuf;
    __half* Wsh = (__half*)(smbuf + 128 * XS2_LD * 2);
    float*  osh = (float*)smbuf;           // aliases after mainloop (needs 20480 B)

    int tid = threadIdx.x;
    int row0 = blockIdx.x * 128;

    // W2 64x32 fp32 -> fp16 smem.
    const float4* W4 = (const float4*)W;
    for (int i = tid; i < FH * FO / 4; i += 256) {
        int k = i >> 3, c4 = i & 7;
        float4 v = W4[i];
        __half2 h01 = __float22half2_rn(make_float2(v.x, v.y));
        __half2 h23 = __float22half2_rn(make_float2(v.z, v.w));
        uint2 u; u.x = *(unsigned*)&h01; u.y = *(unsigned*)&h23;
        *(uint2*)&Wsh[k * WS2_LD + c4 * 4] = u;
    }
    // a1 tile 128x64 fp16 -> smem (straight uint2 copies).
    const uint2* a1v = (const uint2*)g_a1h;    // 16 uint2 per row
    for (int i = tid; i < 128 * 16; i += 256) {
        int r = i >> 4, c4 = i & 15;
        int row = row0 + r;
        uint2 u = make_uint2(0u, 0u);
        if (row < NN) u = a1v[(size_t)row * 16 + c4];
        *(uint2*)&xsh[r * XS2_LD + c4 * 4] = u;
    }
    __syncthreads();

    int warp = tid >> 5;           // 0..7 : rows warp*16, all 32 cols

    wmma::fragment<wmma::matrix_a, 16, 16, 16, __half, wmma::row_major> af;
    wmma::fragment<wmma::matrix_b, 16, 16, 16, __half, wmma::row_major> bf0, bf1;
    wmma::fragment<wmma::accumulator, 16, 16, 16, float> c0, c1;
    wmma::fill_fragment(c0, 0.f);
    wmma::fill_fragment(c1, 0.f);

    #pragma unroll
    for (int k = 0; k < 4; k++) {
        wmma::load_matrix_sync(af, xsh + warp * 16 * XS2_LD + k * 16, XS2_LD);
        wmma::load_matrix_sync(bf0, Wsh + k * 16 * WS2_LD, WS2_LD);
        wmma::load_matrix_sync(bf1, Wsh + k * 16 * WS2_LD + 16, WS2_LD);
        wmma::mma_sync(c0, af, bf0, c0);
        wmma::mma_sync(c1, af, bf1, c1);
    }

    __syncthreads();
    wmma::store_matrix_sync(osh + warp * 16 * OS2_LD,      c0, OS2_LD, wmma::mem_row_major);
    wmma::store_matrix_sync(osh + warp * 16 * OS2_LD + 16, c1, OS2_LD, wmma::mem_row_major);
    __syncthreads();

    uint2* h3v = (uint2*)g_h3h;            // 8 uint2 per row
    for (int i = tid; i < 128 * 8; i += 256) {
        int r = i >> 3, c4 = i & 7;
        int row = row0 + r;
        if (row < NN) {
            float4 v = *(float4*)&osh[r * OS2_LD + c4 * 4];
            __half2 h01 = __float22half2_rn(make_float2(v.x, v.y));
            __half2 h23 = __float22half2_rn(make_float2(v.z, v.w));
            uint2 u; u.x = *(unsigned*)&h01; u.y = *(unsigned*)&h23;
            h3v[(size_t)row * 8 + c4] = u;
        }
    }
}

// Aggregation layer 2 (+ self-loop + bias): 8 lanes per dst node, each lane
// gathers 4 fp16 features per edge; fp32 accumulate; fp32 store to d_out.
__global__ __launch_bounds__(256) void k_agg2(float* __restrict__ out,
                                              const float* __restrict__ b2) {
    int gid = blockIdx.x * 256 + threadIdx.x;
    int node = gid >> 3;
    int lane = threadIdx.x & 7;
    if (node >= NN) return;
    int off = g_off[node];
    int n   = g_off[node + 1] - off;
    const uint2* h3v = (const uint2*)g_h3h;    // 8 uint2 per row
    float4 acc = make_float4(0.f, 0.f, 0.f, 0.f);

    #define AGG2_TERM(u, nm)                                              \
        do {                                                              \
            __half2 hl = *(__half2*)&(u).x;                               \
            __half2 hh = *(__half2*)&(u).y;                               \
            float2 pl = __half22float2(hl);                               \
            float2 ph = __half22float2(hh);                               \
            acc.x = fmaf(pl.x, nm, acc.x); acc.y = fmaf(pl.y, nm, acc.y); \
            acc.z = fmaf(ph.x, nm, acc.z); acc.w = fmaf(ph.y, nm, acc.w); \
        } while (0)

    int i = 0;
    for (; i + 1 < n; i += 2) {
        int2 e0 = g_edge[off + i];
        int2 e1 = g_edge[off + i + 1];
        uint2 u0 = h3v[(size_t)e0.x * 8 + lane];
        uint2 u1 = h3v[(size_t)e1.x * 8 + lane];
        float n0 = __int_as_float(e0.y), n1 = __int_as_float(e1.y);
        AGG2_TERM(u0, n0);
        AGG2_TERM(u1, n1);
    }
    if (i < n) {
        int2 e0 = g_edge[off + i];
        uint2 u0 = h3v[(size_t)e0.x * 8 + lane];
        float n0 = __int_as_float(e0.y);
        AGG2_TERM(u0, n0);
    }
    {   // self-loop
        float di = g_dinv[node];
        float w = di * di;
        uint2 us = h3v[(size_t)node * 8 + lane];
        AGG2_TERM(us, w);
    }
    #undef AGG2_TERM

    float4 bb = ((const float4*)b2)[lane];
    acc.x += bb.x;
    acc.y += bb.y;
    acc.z += bb.z;
    acc.w += bb.w;
    ((float4*)out)[(size_t)node * 8 + lane] = acc;
}

// ---------------------------------------------------------------------------
namespace {
struct Ctx {
    cudaStream_t s2;
    cudaEvent_t e_fork, e_join;
    Ctx() {
        cudaStreamCreateWithFlags(&s2, cudaStreamNonBlocking);
        cudaEventCreateWithFlags(&e_fork, cudaEventDisableTiming);
        cudaEventCreateWithFlags(&e_join, cudaEventDisableTiming);
    }
};
}

extern "C" void kernel_launch(void* const* d_in, const int* in_sizes, int n_in,
                              void* d_out, int out_size) {
    static Ctx ctx;   // created on first (uncaptured) correctness call

    const float* x  = (const float*)d_in[0];
    const int*   ei = (const int*)d_in[1];     // int32 (JAX x64 disabled)
    const float* W1 = (const float*)d_in[2];
    const float* b1 = (const float*)d_in[3];
    const float* W2 = (const float*)d_in[4];
    const float* b2 = (const float*)d_in[5];
    float* out = (float*)d_out;

    const int E = in_sizes[1] / 2;

    // Fork: graph preprocessing on ctx.s2 concurrently with GEMM1.
    cudaEventRecord(ctx.e_fork, 0);
    cudaStreamWaitEvent(ctx.s2, ctx.e_fork, 0);

    k_deg<<<(E + 255) / 256, 256, 0, ctx.s2>>>(ei, E);
    k_scan<<<NSCAN_BLK, 512, 0, ctx.s2>>>();
    k_scatter<<<(E + 255) / 256, 256, 0, ctx.s2>>>(ei, E);
    cudaEventRecord(ctx.e_join, ctx.s2);

    k_gemm1<<<(NN + 63) / 64, 256>>>(x, W1);

    // Join: aggregation needs both h1 and the grouped edge list.
    cudaStreamWaitEvent(0, ctx.e_join, 0);

    k_agg1<<<(unsigned)(((long)NN * 16 + 255) / 256), 256>>>(b1);
    k_gemm2<<<(NN + 127) / 128, 256>>>(W2);
    k_agg2<<<(unsigned)(((long)NN * 8 + 255) / 256), 256>>>(out, b2);
}